// round 1
// baseline (speedup 1.0000x reference)
#include <cuda_runtime.h>
#include <math.h>

#define N 512
#define NIMG 128
#define NFREQ 257

// ---------------- device scratch (static __device__ = sanctioned scratch path) --------------
static __device__ float2 g_scratch[(size_t)NIMG * N * N];  // 256 MB: row-FFT output, row-major
static __device__ float2 g_tw[N];                          // W_512^k = exp(-2pi i k/512)
static __device__ float  g_meanpart[NIMG * 8];
static __device__ float  g_mean[NIMG];
static __device__ float  g_accum[N * N];                   // sum over batch of |F|^2 (unshifted)
static __device__ float  g_sums[NFREQ];
static __device__ float  g_cnts[NFREQ];

__device__ __forceinline__ int adr(int i)  { return i + (i >> 5); }                 // pad every 32
__device__ __forceinline__ int rev8(int i) { return ((i & 7) << 6) | (i & 56) | (i >> 6); }

__device__ __forceinline__ void cmul(float ar, float ai, float br, float bi,
                                     float& cr, float& ci) {
    cr = ar * br - ai * bi;
    ci = ar * bi + ai * br;
}

// In-place radix-8 DIT FFT of 512 points living in padded smem arrays sre/sim.
// 64 cooperating threads per FFT (fj = 0..63); input must be base-8 digit-reversed.
// Contains block-wide __syncthreads() — every thread of the block must call it.
__device__ __forceinline__ void fft512_block(float* sre, float* sim, int fj) {
#pragma unroll
    for (int s = 0; s < 3; ++s) {
        const int h    = 1 << (3 * s);          // 1, 8, 64
        const int jj   = fj & (h - 1);
        const int g    = fj >> (3 * s);
        const int base = (g << (3 * s + 3)) + jj;
        const int e    = jj << (6 - 3 * s);     // jj * (512/(8h))

        float ar[8], ai[8];
#pragma unroll
        for (int m = 0; m < 8; m++) {
            int p = adr(base + m * h);
            ar[m] = sre[p];
            ai[m] = sim[p];
        }

        // twiddles w^m, m=0..7 ; 3 table loads + 4 cmuls
        float wr[8], wi[8];
        wr[0] = 1.f; wi[0] = 0.f;
        float2 W1 = g_tw[e];     wr[1] = W1.x; wi[1] = W1.y;
        float2 W2 = g_tw[2 * e]; wr[2] = W2.x; wi[2] = W2.y;
        float2 W4 = g_tw[4 * e]; wr[4] = W4.x; wi[4] = W4.y;
        cmul(wr[1], wi[1], wr[2], wi[2], wr[3], wi[3]);
        cmul(wr[1], wi[1], wr[4], wi[4], wr[5], wi[5]);
        cmul(wr[2], wi[2], wr[4], wi[4], wr[6], wi[6]);
        cmul(wr[3], wi[3], wr[4], wi[4], wr[7], wi[7]);

        float tr[8], ti[8];
        tr[0] = ar[0]; ti[0] = ai[0];
#pragma unroll
        for (int m = 1; m < 8; m++) cmul(ar[m], ai[m], wr[m], wi[m], tr[m], ti[m]);

        // 8-point DFT (radix-2 DIT on bit-reversed feed), output natural order
        float b0r = tr[0], b0i = ti[0], b1r = tr[4], b1i = ti[4];
        float b2r = tr[2], b2i = ti[2], b3r = tr[6], b3i = ti[6];
        float b4r = tr[1], b4i = ti[1], b5r = tr[5], b5i = ti[5];
        float b6r = tr[3], b6i = ti[3], b7r = tr[7], b7i = ti[7];

        float u0r = b0r + b1r, u0i = b0i + b1i, u1r = b0r - b1r, u1i = b0i - b1i;
        float u2r = b2r + b3r, u2i = b2i + b3i, u3r = b2r - b3r, u3i = b2i - b3i;
        float u4r = b4r + b5r, u4i = b4i + b5i, u5r = b4r - b5r, u5i = b4i - b5i;
        float u6r = b6r + b7r, u6i = b6i + b7i, u7r = b6r - b7r, u7i = b6i - b7i;

        float v0r = u0r + u2r, v0i = u0i + u2i, v2r = u0r - u2r, v2i = u0i - u2i;
        float v1r = u1r + u3i, v1i = u1i - u3r, v3r = u1r - u3i, v3i = u1i + u3r;
        float v4r = u4r + u6r, v4i = u4i + u6i, v6r = u4r - u6r, v6i = u4i - u6i;
        float v5r = u5r + u7i, v5i = u5i - u7r, v7r = u5r - u7i, v7i = u5i + u7r;

        const float C = 0.70710678118654752f;
        float a5r = C * (v5r + v5i), a5i = C * (v5i - v5r);   // W8^1 * v5
        float a7r = C * (v7i - v7r), a7i = -C * (v7r + v7i);  // W8^3 * v7

        float y0r = v0r + v4r, y0i = v0i + v4i, y4r = v0r - v4r, y4i = v0i - v4i;
        float y1r = v1r + a5r, y1i = v1i + a5i, y5r = v1r - a5r, y5i = v1i - a5i;
        float y2r = v2r + v6i, y2i = v2i - v6r, y6r = v2r - v6i, y6i = v2i + v6r;
        float y3r = v3r + a7r, y3i = v3i + a7i, y7r = v3r - a7r, y7i = v3i - a7i;

        int p0 = adr(base);
        sre[p0] = y0r; sim[p0] = y0i;
        int p1 = adr(base + 1 * h); sre[p1] = y1r; sim[p1] = y1i;
        int p2 = adr(base + 2 * h); sre[p2] = y2r; sim[p2] = y2i;
        int p3 = adr(base + 3 * h); sre[p3] = y3r; sim[p3] = y3i;
        int p4 = adr(base + 4 * h); sre[p4] = y4r; sim[p4] = y4i;
        int p5 = adr(base + 5 * h); sre[p5] = y5r; sim[p5] = y5i;
        int p6 = adr(base + 6 * h); sre[p6] = y6r; sim[p6] = y6i;
        int p7 = adr(base + 7 * h); sre[p7] = y7r; sim[p7] = y7i;
        __syncthreads();
    }
}

// ---------------- kernel 0: zero accumulators, fill twiddle table --------------------------
__global__ void k_init() {
    int p = blockIdx.x * blockDim.x + threadIdx.x;
    if (p < N * N) g_accum[p] = 0.f;
    if (p < N) {
        double ang = -6.283185307179586476925286766559 * (double)p / 512.0;
        g_tw[p] = make_float2((float)cos(ang), (float)sin(ang));
    }
    if (p < NFREQ) { g_sums[p] = 0.f; g_cnts[p] = 0.f; }
}

// ---------------- kernel 1: per-image partial sums (deterministic two-stage) ---------------
__global__ void __launch_bounds__(256) k_meanpart(const float* __restrict__ x) {
    int img = blockIdx.x >> 3, part = blockIdx.x & 7;
    const float4* x4 = (const float4*)x;
    size_t base = ((size_t)img << 16) + ((size_t)part << 13);  // float4 units
    float s = 0.f;
#pragma unroll
    for (int k = 0; k < 32; k++) {
        float4 v = x4[base + threadIdx.x + (k << 8)];
        s += (v.x + v.y) + (v.z + v.w);
    }
    __shared__ float red[8];
#pragma unroll
    for (int o = 16; o; o >>= 1) s += __shfl_down_sync(0xffffffffu, s, o);
    if ((threadIdx.x & 31) == 0) red[threadIdx.x >> 5] = s;
    __syncthreads();
    if (threadIdx.x < 8) {
        s = red[threadIdx.x];
#pragma unroll
        for (int o = 4; o; o >>= 1) s += __shfl_down_sync(0xffu, s, o);
        if (threadIdx.x == 0) g_meanpart[blockIdx.x] = s;
    }
}

__global__ void k_meanfin() {
    int i = threadIdx.x;
    if (i < NIMG) {
        float s = 0.f;
#pragma unroll
        for (int p = 0; p < 8; p++) s += g_meanpart[i * 8 + p];
        g_mean[i] = s * (1.0f / 262144.0f);
    }
}

// ---------------- kernel 2: row FFTs (4 rows per block), (x-mean)*hann applied -------------
__global__ void __launch_bounds__(256) k_rowfft(const float* __restrict__ x) {
    __shared__ float sre[4][528], sim[4][528];
    int b  = blockIdx.x >> 7;
    int r0 = (blockIdx.x & 127) << 2;
    float mean = g_mean[b];
    int tid = threadIdx.x;
    const float STEP = 512.0f / 511.0f;

#pragma unroll
    for (int k = 0; k < 8; k++) {
        int li = tid + (k << 8);
        int row = li >> 9, c = li & 511;
        float v  = x[((size_t)b << 18) + ((size_t)(r0 + row) << 9) + c];
        float lc = fmaf((float)c,          STEP, -256.0f);
        float lr = fmaf((float)(r0 + row), STEP, -256.0f);
        float rd = sqrtf(lc * lc + lr * lr);
        float h  = (rd > 256.0f) ? 0.0f : 0.5f * (1.0f + cospif(rd * (1.0f / 256.0f)));
        int p = adr(rev8(c));
        sre[row][p] = (v - mean) * h;
        sim[row][p] = 0.0f;
    }
    __syncthreads();

    int frow = tid >> 6, fj = tid & 63;
    fft512_block(sre[frow], sim[frow], fj);

#pragma unroll
    for (int k = 0; k < 8; k++) {
        int li = tid + (k << 8);
        int row = li >> 9, c = li & 511;
        int p = adr(c);
        g_scratch[((size_t)b << 18) + ((size_t)(r0 + row) << 9) + c] =
            make_float2(sre[row][p], sim[row][p]);
    }
}

// ---------------- kernel 3: column FFTs, 8 cols x 8 images per block, |F|^2 accumulate -----
__global__ void __launch_bounds__(512) k_colfft() {
    __shared__ float sre[8][528], sim[8][528];
    int ct  = blockIdx.x & 63;
    int grp = blockIdx.x >> 6;
    int c0  = ct << 3;
    int tid = threadIdx.x;

    float acc[8];
#pragma unroll
    for (int k = 0; k < 8; k++) acc[k] = 0.f;

    for (int bi = 0; bi < 8; ++bi) {
        int b = (grp << 3) + bi;
        __syncthreads();  // previous iter's accumulate reads done before overwriting
#pragma unroll
        for (int k = 0; k < 8; k++) {
            int li = tid + (k << 9);
            int r = li >> 3, cl = li & 7;
            float2 v = g_scratch[((size_t)b << 18) + ((size_t)r << 9) + c0 + cl];
            int p = adr(rev8(r));
            sre[cl][p] = v.x;
            sim[cl][p] = v.y;
        }
        __syncthreads();

        int col = tid >> 6, fj = tid & 63;
        fft512_block(sre[col], sim[col], fj);  // ends with __syncthreads()

#pragma unroll
        for (int k = 0; k < 8; k++) {
            int li = tid + (k << 9);
            int r = li >> 3, cl = li & 7;
            int p = adr(r);
            float re = sre[cl][p], im = sim[cl][p];
            acc[k] = fmaf(re, re, fmaf(im, im, acc[k]));
        }
    }

#pragma unroll
    for (int k = 0; k < 8; k++) {
        int li = tid + (k << 9);
        int r = li >> 3, cl = li & 7;
        atomicAdd(&g_accum[(r << 9) + c0 + cl], acc[k]);
    }
}

// ---------------- kernel 4: nps2D (shift + scale) + radial bin accumulation ----------------
__global__ void k_finalize2d(float* __restrict__ out) {
    int p = blockIdx.x * blockDim.x + threadIdx.x;
    if (p >= N * N) return;
    int i = p >> 9, j = p & 511;
    const float SC = (float)(0.01 / (262144.0 * 128.0));  // px^2/roi^2 * 1/batch
    float val = g_accum[((i ^ 256) << 9) + (j ^ 256)] * SC;
    out[NFREQ + p] = val;  // nps2D

    int xi = i - 256, yj = j - 256;
    int rad = __double2int_rn(sqrt((double)(xi * xi + yj * yj)));
    if (rad < NFREQ) {
        atomicAdd(&g_sums[rad], val);
        atomicAdd(&g_cnts[rad], 1.0f);
    }
}

// ---------------- kernel 5: nps1D and f1D --------------------------------------------------
__global__ void k_finalize1d(float* __restrict__ out) {
    int k = threadIdx.x;
    if (k < NFREQ) {
        out[k] = g_sums[k] / g_cnts[k];                       // nps1D
        out[NFREQ + N * N + k] = 5.0f * (float)k / 256.0f;    // f1D (nyquist = 1/(2*0.1))
    }
}

extern "C" void kernel_launch(void* const* d_in, const int* in_sizes, int n_in,
                              void* d_out, int out_size) {
    const float* x = (const float*)d_in[0];
    float* out = (float*)d_out;

    k_init<<<1024, 256>>>();
    k_meanpart<<<NIMG * 8, 256>>>(x);
    k_meanfin<<<1, 128>>>();
    k_rowfft<<<NIMG * 128, 256>>>(x);   // 4 rows per block
    k_colfft<<<64 * 16, 512>>>();       // 64 col-tiles x 16 image-groups
    k_finalize2d<<<(N * N + 255) / 256, 256>>>(out);
    k_finalize1d<<<1, NFREQ>>>(out);
}

// round 2
// speedup vs baseline: 1.4922x; 1.4922x over previous
#include <cuda_runtime.h>
#include <math.h>

#define N 512
#define NIMG 128
#define NFREQ 257
#define SCW 264   // padded scratch width (float2 units), multiple of 8

// ---------------- device scratch ------------------------------------------------------------
static __device__ float2 g_scratch[(size_t)NIMG * N * SCW];  // ~138 MB: row-FFT out, cols 0..256
static __device__ float2 g_tw[N];                            // W_512^k
static __device__ float  g_meanpart[NIMG * 8];
static __device__ float  g_mean[NIMG];
static __device__ float  g_accum[N * NFREQ];                 // half-plane sum |F|^2 (unshifted)
static __device__ float  g_sums[NFREQ];
static __device__ float  g_cnts[NFREQ];

__device__ __forceinline__ int adr(int i)  { return i + (i >> 5); }
__device__ __forceinline__ int rev8(int i) { return ((i & 7) << 6) | (i & 56) | (i >> 6); }

__device__ __forceinline__ void cmul(float ar, float ai, float br, float bi,
                                     float& cr, float& ci) {
    cr = ar * br - ai * bi;
    ci = ar * bi + ai * br;
}

// In-place radix-8 DIT FFT of 512 points in padded smem arrays. 64 threads per FFT.
// Input base-8 digit-reversed; output natural order. Block-wide syncs inside.
__device__ __forceinline__ void fft512_block(float* sre, float* sim, int fj) {
#pragma unroll
    for (int s = 0; s < 3; ++s) {
        const int h    = 1 << (3 * s);
        const int jj   = fj & (h - 1);
        const int g    = fj >> (3 * s);
        const int base = (g << (3 * s + 3)) + jj;
        const int e    = jj << (6 - 3 * s);

        float ar[8], ai[8];
#pragma unroll
        for (int m = 0; m < 8; m++) {
            int p = adr(base + m * h);
            ar[m] = sre[p];
            ai[m] = sim[p];
        }

        float wr[8], wi[8];
        wr[0] = 1.f; wi[0] = 0.f;
        float2 W1 = g_tw[e];     wr[1] = W1.x; wi[1] = W1.y;
        float2 W2 = g_tw[2 * e]; wr[2] = W2.x; wi[2] = W2.y;
        float2 W4 = g_tw[4 * e]; wr[4] = W4.x; wi[4] = W4.y;
        cmul(wr[1], wi[1], wr[2], wi[2], wr[3], wi[3]);
        cmul(wr[1], wi[1], wr[4], wi[4], wr[5], wi[5]);
        cmul(wr[2], wi[2], wr[4], wi[4], wr[6], wi[6]);
        cmul(wr[3], wi[3], wr[4], wi[4], wr[7], wi[7]);

        float tr[8], ti[8];
        tr[0] = ar[0]; ti[0] = ai[0];
#pragma unroll
        for (int m = 1; m < 8; m++) cmul(ar[m], ai[m], wr[m], wi[m], tr[m], ti[m]);

        float b0r = tr[0], b0i = ti[0], b1r = tr[4], b1i = ti[4];
        float b2r = tr[2], b2i = ti[2], b3r = tr[6], b3i = ti[6];
        float b4r = tr[1], b4i = ti[1], b5r = tr[5], b5i = ti[5];
        float b6r = tr[3], b6i = ti[3], b7r = tr[7], b7i = ti[7];

        float u0r = b0r + b1r, u0i = b0i + b1i, u1r = b0r - b1r, u1i = b0i - b1i;
        float u2r = b2r + b3r, u2i = b2i + b3i, u3r = b2r - b3r, u3i = b2i - b3i;
        float u4r = b4r + b5r, u4i = b4i + b5i, u5r = b4r - b5r, u5i = b4i - b5i;
        float u6r = b6r + b7r, u6i = b6i + b7i, u7r = b6r - b7r, u7i = b6i - b7i;

        float v0r = u0r + u2r, v0i = u0i + u2i, v2r = u0r - u2r, v2i = u0i - u2i;
        float v1r = u1r + u3i, v1i = u1i - u3r, v3r = u1r - u3i, v3i = u1i + u3r;
        float v4r = u4r + u6r, v4i = u4i + u6i, v6r = u4r - u6r, v6i = u4i - u6i;
        float v5r = u5r + u7i, v5i = u5i - u7r, v7r = u5r - u7i, v7i = u5i + u7r;

        const float C = 0.70710678118654752f;
        float a5r = C * (v5r + v5i), a5i = C * (v5i - v5r);
        float a7r = C * (v7i - v7r), a7i = -C * (v7r + v7i);

        float y0r = v0r + v4r, y0i = v0i + v4i, y4r = v0r - v4r, y4i = v0i - v4i;
        float y1r = v1r + a5r, y1i = v1i + a5i, y5r = v1r - a5r, y5i = v1i - a5i;
        float y2r = v2r + v6i, y2i = v2i - v6r, y6r = v2r - v6i, y6i = v2i + v6r;
        float y3r = v3r + a7r, y3i = v3i + a7i, y7r = v3r - a7r, y7i = v3i - a7i;

        int p0 = adr(base);
        sre[p0] = y0r; sim[p0] = y0i;
        int p1 = adr(base + 1 * h); sre[p1] = y1r; sim[p1] = y1i;
        int p2 = adr(base + 2 * h); sre[p2] = y2r; sim[p2] = y2i;
        int p3 = adr(base + 3 * h); sre[p3] = y3r; sim[p3] = y3i;
        int p4 = adr(base + 4 * h); sre[p4] = y4r; sim[p4] = y4i;
        int p5 = adr(base + 5 * h); sre[p5] = y5r; sim[p5] = y5i;
        int p6 = adr(base + 6 * h); sre[p6] = y6r; sim[p6] = y6i;
        int p7 = adr(base + 7 * h); sre[p7] = y7r; sim[p7] = y7i;
        __syncthreads();
    }
}

// ---------------- kernel 0: init -------------------------------------------------------------
__global__ void k_init() {
    int p = blockIdx.x * blockDim.x + threadIdx.x;
    if (p < N * NFREQ) g_accum[p] = 0.f;
    if (p < N) {
        double ang = -6.283185307179586476925286766559 * (double)p / 512.0;
        g_tw[p] = make_float2((float)cos(ang), (float)sin(ang));
    }
    if (p < NFREQ) { g_sums[p] = 0.f; g_cnts[p] = 0.f; }
}

// ---------------- kernel 1: per-image means --------------------------------------------------
__global__ void __launch_bounds__(256) k_meanpart(const float* __restrict__ x) {
    int img = blockIdx.x >> 3, part = blockIdx.x & 7;
    const float4* x4 = (const float4*)x;
    size_t base = ((size_t)img << 16) + ((size_t)part << 13);
    float s = 0.f;
#pragma unroll
    for (int k = 0; k < 32; k++) {
        float4 v = x4[base + threadIdx.x + (k << 8)];
        s += (v.x + v.y) + (v.z + v.w);
    }
    __shared__ float red[8];
#pragma unroll
    for (int o = 16; o; o >>= 1) s += __shfl_down_sync(0xffffffffu, s, o);
    if ((threadIdx.x & 31) == 0) red[threadIdx.x >> 5] = s;
    __syncthreads();
    if (threadIdx.x < 8) {
        s = red[threadIdx.x];
#pragma unroll
        for (int o = 4; o; o >>= 1) s += __shfl_down_sync(0xffu, s, o);
        if (threadIdx.x == 0) g_meanpart[blockIdx.x] = s;
    }
}

__global__ void k_meanfin() {
    int i = threadIdx.x;
    if (i < NIMG) {
        float s = 0.f;
#pragma unroll
        for (int p = 0; p < 8; p++) s += g_meanpart[i * 8 + p];
        g_mean[i] = s * (1.0f / 262144.0f);
    }
}

// ---------------- kernel 2: row FFTs — 2 real rows packed per complex FFT --------------------
// 8 rows per block (4 packed FFTs), 256 threads. Stores only k=0..256 per row.
__global__ void __launch_bounds__(256) k_rowfft(const float* __restrict__ x) {
    __shared__ float sre[4][528], sim[4][528];
    int b  = blockIdx.x >> 6;              // 64 blocks per image
    int r0 = (blockIdx.x & 63) << 3;       // 8 rows
    float mean = g_mean[b];
    int tid = threadIdx.x;
    const float STEP = 512.0f / 511.0f;

#pragma unroll
    for (int k = 0; k < 16; k++) {
        int li  = tid + (k << 8);          // 0..4095
        int row = li >> 9, c = li & 511;
        float v  = x[((size_t)b << 18) + ((size_t)(r0 + row) << 9) + c];
        float lc = fmaf((float)c,          STEP, -256.0f);
        float lr = fmaf((float)(r0 + row), STEP, -256.0f);
        float rd = sqrtf(lc * lc + lr * lr);
        float h  = (rd > 256.0f) ? 0.0f : 0.5f * (1.0f + cospif(rd * (1.0f / 256.0f)));
        float w  = (v - mean) * h;
        int f = row >> 1, p = adr(rev8(c));
        if (row & 1) sim[f][p] = w;
        else         sre[f][p] = w;
    }
    __syncthreads();

    fft512_block(sre[tid >> 6], sim[tid >> 6], tid & 63);

    // unpack A/B spectra for k=0..256, store to scratch (row-major, width SCW)
    size_t rowbase = ((size_t)b << 9) + r0;   // in rows
#pragma unroll
    for (int it = 0; it < 5; it++) {
        int idx = tid + (it << 8);
        if (idx < 4 * NFREQ) {
            int f = idx / NFREQ;
            int k = idx - f * NFREQ;
            int nk = (512 - k) & 511;
            float zr = sre[f][adr(k)],  zi = sim[f][adr(k)];
            float yr = sre[f][adr(nk)], yi = sim[f][adr(nk)];
            float2 A = make_float2(0.5f * (zr + yr), 0.5f * (zi - yi));
            float2 B = make_float2(0.5f * (zi + yi), 0.5f * (yr - zr));
            g_scratch[(rowbase + 2 * f)     * SCW + k] = A;
            g_scratch[(rowbase + 2 * f + 1) * SCW + k] = B;
        }
    }
}

// ---------------- kernel 3: column FFTs over cols 0..256 only -------------------------------
// 33 col-tiles x 16 image-groups; 8 cols x 8 images per block; |F|^2 batch-accumulated in regs.
__global__ void __launch_bounds__(512) k_colfft() {
    __shared__ float sre[8][528], sim[8][528];
    int ct  = blockIdx.x % 33;
    int grp = blockIdx.x / 33;
    int c0  = ct << 3;
    int tid = threadIdx.x;

    float acc[8];
#pragma unroll
    for (int k = 0; k < 8; k++) acc[k] = 0.f;

    for (int bi = 0; bi < 8; ++bi) {
        int b = (grp << 3) + bi;
        __syncthreads();
#pragma unroll
        for (int k = 0; k < 8; k++) {
            int li = tid + (k << 9);
            int r = li >> 3, cl = li & 7;
            int c = c0 + cl;
            float2 v = (c < NFREQ)
                ? g_scratch[(((size_t)b << 9) + r) * SCW + c]
                : make_float2(0.f, 0.f);
            int p = adr(rev8(r));
            sre[cl][p] = v.x;
            sim[cl][p] = v.y;
        }
        __syncthreads();

        fft512_block(sre[tid >> 6], sim[tid >> 6], tid & 63);

#pragma unroll
        for (int k = 0; k < 8; k++) {
            int li = tid + (k << 9);
            int r = li >> 3, cl = li & 7;
            int p = adr(r);
            float re = sre[cl][p], im = sim[cl][p];
            acc[k] = fmaf(re, re, fmaf(im, im, acc[k]));
        }
    }

#pragma unroll
    for (int k = 0; k < 8; k++) {
        int li = tid + (k << 9);
        int r = li >> 3, cl = li & 7;
        int c = c0 + cl;
        if (c < NFREQ) atomicAdd(&g_accum[r * NFREQ + c], acc[k]);
    }
}

// ---------------- kernel 4: nps2D via Hermitian mirror + radial binning ---------------------
__global__ void k_finalize2d(float* __restrict__ out) {
    int p = blockIdx.x * blockDim.x + threadIdx.x;
    if (p >= N * N) return;
    int i = p >> 9, j = p & 511;
    int u = i ^ 256, v = j ^ 256;                 // unshifted freq indices
    if (v > 256) { u = (512 - u) & 511; v = 512 - v; }   // Hermitian mirror
    const float SC = (float)(0.01 / (262144.0 * 128.0));
    float val = g_accum[u * NFREQ + v] * SC;
    out[NFREQ + p] = val;

    int xi = i - 256, yj = j - 256;
    int rad = __double2int_rn(sqrt((double)(xi * xi + yj * yj)));
    if (rad < NFREQ) {
        atomicAdd(&g_sums[rad], val);
        atomicAdd(&g_cnts[rad], 1.0f);
    }
}

// ---------------- kernel 5: nps1D and f1D ----------------------------------------------------
__global__ void k_finalize1d(float* __restrict__ out) {
    int k = threadIdx.x;
    if (k < NFREQ) {
        out[k] = g_sums[k] / g_cnts[k];
        out[NFREQ + N * N + k] = 5.0f * (float)k / 256.0f;
    }
}

extern "C" void kernel_launch(void* const* d_in, const int* in_sizes, int n_in,
                              void* d_out, int out_size) {
    const float* x = (const float*)d_in[0];
    float* out = (float*)d_out;

    k_init<<<1024, 256>>>();
    k_meanpart<<<NIMG * 8, 256>>>(x);
    k_meanfin<<<1, 128>>>();
    k_rowfft<<<NIMG * 64, 256>>>(x);    // 8 rows (4 packed FFTs) per block
    k_colfft<<<33 * 16, 512>>>();       // 33 col-tiles x 16 image-groups
    k_finalize2d<<<(N * N + 255) / 256, 256>>>(out);
    k_finalize1d<<<1, NFREQ>>>(out);
}

// round 3
// speedup vs baseline: 1.6062x; 1.0764x over previous
#include <cuda_runtime.h>
#include <math.h>

#define N 512
#define NIMG 128
#define NFREQ 257
#define SCW 264   // padded scratch width (float2 units)

// ---------------- device scratch ------------------------------------------------------------
static __device__ float2 g_scratch[(size_t)NIMG * N * SCW];  // row-FFT out, cols 0..256
static __device__ float2 g_tw[N];                            // W_512^k
static __device__ float  g_meanpart[NIMG * 8];
static __device__ float  g_mean[NIMG];
static __device__ float  g_accum[N * NFREQ];                 // half-plane sum |F|^2 (unshifted)
static __device__ float  g_psum[32][NFREQ];
static __device__ float  g_pcnt[32][NFREQ];

__device__ __forceinline__ int adr2(int i) { return i + (i >> 3); }   // float2 pad-every-8
__device__ __forceinline__ int rev8(int i) { return ((i & 7) << 6) | (i & 56) | (i >> 6); }

// ---- packed f32x2 helpers (sm_103a) ---------------------------------------------------------
union F2U { float2 f; unsigned long long u; };

__device__ __forceinline__ float2 padd(float2 a, float2 b) {
    F2U A, B, C; A.f = a; B.f = b;
    asm("add.rn.f32x2 %0, %1, %2;" : "=l"(C.u) : "l"(A.u), "l"(B.u));
    return C.f;
}
__device__ __forceinline__ float2 psub(float2 a, float2 b) {  // a - b  (exact: fma(b,-1,a))
    F2U A, B, C; A.f = a; B.f = b;
    asm("fma.rn.f32x2 %0, %1, %2, %3;"
        : "=l"(C.u) : "l"(B.u), "l"(0xBF800000BF800000ULL), "l"(A.u));
    return C.f;
}
__device__ __forceinline__ float2 cmulf2(float2 a, float2 w) {
    return make_float2(a.x * w.x - a.y * w.y, a.x * w.y + a.y * w.x);
}

// ---- 8-point DFT, natural-order in t[0..7] (pre-twiddled), natural-order out ----------------
__device__ __forceinline__ void dft8(float2* t) {
    float2 b0 = t[0], b1 = t[4], b2 = t[2], b3 = t[6];
    float2 b4 = t[1], b5 = t[5], b6 = t[3], b7 = t[7];
    float2 u0 = padd(b0, b1), u1 = psub(b0, b1), u2 = padd(b2, b3), u3 = psub(b2, b3);
    float2 u4 = padd(b4, b5), u5 = psub(b4, b5), u6 = padd(b6, b7), u7 = psub(b6, b7);
    float2 v0 = padd(u0, u2), v2 = psub(u0, u2);
    float2 v1 = make_float2(u1.x + u3.y, u1.y - u3.x);
    float2 v3 = make_float2(u1.x - u3.y, u1.y + u3.x);
    float2 v4 = padd(u4, u6), v6 = psub(u4, u6);
    float2 v5 = make_float2(u5.x + u7.y, u5.y - u7.x);
    float2 v7 = make_float2(u5.x - u7.y, u5.y + u7.x);
    const float C = 0.70710678118654752f;
    float2 a5 = make_float2(C * (v5.x + v5.y), C * (v5.y - v5.x));
    float2 a7 = make_float2(C * (v7.y - v7.x), -C * (v7.x + v7.y));
    t[0] = padd(v0, v4); t[4] = psub(v0, v4);
    t[1] = padd(v1, a5); t[5] = psub(v1, a5);
    t[2] = make_float2(v2.x + v6.y, v2.y - v6.x);
    t[6] = make_float2(v2.x - v6.y, v2.y + v6.x);
    t[3] = padd(v3, a7); t[7] = psub(v3, a7);
}

// ---- in-place radix-8 512-pt FFT in padded float2 smem; 64 threads per FFT ------------------
// input base-8 digit-reversed; output natural order; contains block-wide syncs.
__device__ __forceinline__ void fft512f2(float2* s, int fj) {
    // stage 0: stride 1, twiddles == 1
    {
        int pb = 9 * fj;                 // adr2(8*fj + m) = 9*fj + m  (m<8)
        float2 t[8];
#pragma unroll
        for (int m = 0; m < 8; m++) t[m] = s[pb + m];
        dft8(t);
#pragma unroll
        for (int m = 0; m < 8; m++) s[pb + m] = t[m];
    }
    __syncthreads();
    // stage 1: stride 8, e = (fj&7)*8
    {
        int jj = fj & 7;
        int pb = 72 * (fj >> 3) + jj;    // adr2(64g + jj + 8m) = 72g + jj + 9m
        float2 t[8];
#pragma unroll
        for (int m = 0; m < 8; m++) t[m] = s[pb + 9 * m];
#pragma unroll
        for (int m = 1; m < 8; m++) t[m] = cmulf2(t[m], g_tw[(m * jj) << 3]);
        dft8(t);
#pragma unroll
        for (int m = 0; m < 8; m++) s[pb + 9 * m] = t[m];
    }
    __syncthreads();
    // stage 2: stride 64, e = fj
    {
        int pb = fj + (fj >> 3);         // adr2(fj + 64m) = fj + (fj>>3) + 72m
        float2 t[8];
#pragma unroll
        for (int m = 0; m < 8; m++) t[m] = s[pb + 72 * m];
#pragma unroll
        for (int m = 1; m < 8; m++) t[m] = cmulf2(t[m], g_tw[m * fj]);
        dft8(t);
#pragma unroll
        for (int m = 0; m < 8; m++) s[pb + 72 * m] = t[m];
    }
    __syncthreads();
}

// ---------------- kernel 0: init -------------------------------------------------------------
__global__ void k_init() {
    int p = blockIdx.x * blockDim.x + threadIdx.x;
    if (p < N * NFREQ) g_accum[p] = 0.f;
    if (p < N) {
        double ang = -6.283185307179586476925286766559 * (double)p / 512.0;
        g_tw[p] = make_float2((float)cos(ang), (float)sin(ang));
    }
    if (p < 32 * NFREQ) {
        ((float*)g_psum)[p] = 0.f;
        ((float*)g_pcnt)[p] = 0.f;
    }
}

// ---------------- kernel 1: per-image means --------------------------------------------------
__global__ void __launch_bounds__(256) k_meanpart(const float* __restrict__ x) {
    int img = blockIdx.x >> 3, part = blockIdx.x & 7;
    const float4* x4 = (const float4*)x;
    size_t base = ((size_t)img << 16) + ((size_t)part << 13);
    float s = 0.f;
#pragma unroll
    for (int k = 0; k < 32; k++) {
        float4 v = x4[base + threadIdx.x + (k << 8)];
        s += (v.x + v.y) + (v.z + v.w);
    }
    __shared__ float red[8];
#pragma unroll
    for (int o = 16; o; o >>= 1) s += __shfl_down_sync(0xffffffffu, s, o);
    if ((threadIdx.x & 31) == 0) red[threadIdx.x >> 5] = s;
    __syncthreads();
    if (threadIdx.x < 8) {
        s = red[threadIdx.x];
#pragma unroll
        for (int o = 4; o; o >>= 1) s += __shfl_down_sync(0xffu, s, o);
        if (threadIdx.x == 0) g_meanpart[blockIdx.x] = s;
    }
}

__global__ void k_meanfin() {
    int i = threadIdx.x;
    if (i < NIMG) {
        float s = 0.f;
#pragma unroll
        for (int p = 0; p < 8; p++) s += g_meanpart[i * 8 + p];
        g_mean[i] = s * (1.0f / 262144.0f);
    }
}

// ---------------- kernel 2: row FFTs — 2 real rows packed per complex FFT --------------------
__global__ void __launch_bounds__(256) k_rowfft(const float* __restrict__ x) {
    __shared__ float2 sm[4][576];
    int b  = blockIdx.x >> 6;
    int r0 = (blockIdx.x & 63) << 3;
    float mean = g_mean[b];
    int tid = threadIdx.x;
    const float STEP = 512.0f / 511.0f;

#pragma unroll
    for (int k = 0; k < 16; k++) {
        int li  = tid + (k << 8);
        int row = li >> 9, c = li & 511;
        float v  = x[((size_t)b << 18) + ((size_t)(r0 + row) << 9) + c];
        float lc = fmaf((float)c,          STEP, -256.0f);
        float lr = fmaf((float)(r0 + row), STEP, -256.0f);
        float rd = sqrtf(lc * lc + lr * lr);
        float h  = (rd > 256.0f) ? 0.0f : 0.5f * (1.0f + cospif(rd * (1.0f / 256.0f)));
        float w  = (v - mean) * h;
        int f = row >> 1, p = adr2(rev8(c));
        if (row & 1) sm[f][p].y = w;
        else         sm[f][p].x = w;
    }
    __syncthreads();

    fft512f2(sm[tid >> 6], tid & 63);

    size_t rowbase = ((size_t)b << 9) + r0;
#pragma unroll
    for (int it = 0; it < 5; it++) {
        int idx = tid + (it << 8);
        if (idx < 4 * NFREQ) {
            int f = idx / NFREQ;
            int k = idx - f * NFREQ;
            int nk = (512 - k) & 511;
            float2 z = sm[f][adr2(k)];
            float2 y = sm[f][adr2(nk)];
            float2 A = make_float2(0.5f * (z.x + y.x), 0.5f * (z.y - y.y));
            float2 B = make_float2(0.5f * (z.y + y.y), 0.5f * (y.x - z.x));
            g_scratch[(rowbase + 2 * f)     * SCW + k] = A;
            g_scratch[(rowbase + 2 * f + 1) * SCW + k] = B;
        }
    }
}

// ---------------- kernel 3: column FFTs over cols 0..256 -------------------------------------
__global__ void __launch_bounds__(512) k_colfft() {
    __shared__ float2 sm[8][576];
    int ct  = blockIdx.x % 33;
    int grp = blockIdx.x / 33;
    int c0  = ct << 3;
    int tid = threadIdx.x;

    float acc[8];
#pragma unroll
    for (int k = 0; k < 8; k++) acc[k] = 0.f;

    for (int bi = 0; bi < 8; ++bi) {
        int b = (grp << 3) + bi;
        __syncthreads();
#pragma unroll
        for (int k = 0; k < 8; k++) {
            int li = tid + (k << 9);
            int r = li >> 3, cl = li & 7;
            int c = c0 + cl;
            float2 v = (c < NFREQ)
                ? g_scratch[(((size_t)b << 9) + r) * SCW + c]
                : make_float2(0.f, 0.f);
            sm[cl][adr2(rev8(r))] = v;
        }
        __syncthreads();

        fft512f2(sm[tid >> 6], tid & 63);

#pragma unroll
        for (int k = 0; k < 8; k++) {
            int li = tid + (k << 9);
            int r = li >> 3, cl = li & 7;
            float2 v = sm[cl][adr2(r)];
            acc[k] = fmaf(v.x, v.x, fmaf(v.y, v.y, acc[k]));
        }
    }

#pragma unroll
    for (int k = 0; k < 8; k++) {
        int li = tid + (k << 9);
        int r = li >> 3, cl = li & 7;
        int c = c0 + cl;
        if (c < NFREQ) atomicAdd(&g_accum[r * NFREQ + c], acc[k]);
    }
}

// ---------------- kernel 4: nps2D + two-level radial binning --------------------------------
// one block per output row i; 256 threads, 2 pixels each.
__global__ void __launch_bounds__(256) k_finalize2d(float* __restrict__ out) {
    __shared__ float ssum[NFREQ];
    __shared__ float scnt[NFREQ];
    int i = blockIdx.x;
    int tid = threadIdx.x;
    if (tid < NFREQ) { ssum[tid] = 0.f; scnt[tid] = 0.f; }
    if (tid + 256 < NFREQ) { ssum[tid + 256] = 0.f; scnt[tid + 256] = 0.f; }
    __syncthreads();

    const float SC = (float)(0.01 / (262144.0 * 128.0));
    int xi = i - 256;
#pragma unroll
    for (int h = 0; h < 2; h++) {
        int j = tid + (h << 8);
        int u = i ^ 256, v = j ^ 256;
        if (v > 256) { u = (512 - u) & 511; v = 512 - v; }
        float val = g_accum[u * NFREQ + v] * SC;
        out[NFREQ + (i << 9) + j] = val;
        int yj = j - 256;
        int rad = __double2int_rn(sqrt((double)(xi * xi + yj * yj)));
        if (rad < NFREQ) {
            atomicAdd(&ssum[rad], val);
            atomicAdd(&scnt[rad], 1.0f);
        }
    }
    __syncthreads();

    int part = i & 31;
    if (tid < NFREQ) {
        if (ssum[tid] != 0.f || scnt[tid] != 0.f) {
            atomicAdd(&g_psum[part][tid], ssum[tid]);
            atomicAdd(&g_pcnt[part][tid], scnt[tid]);
        }
    }
    if (tid + 256 < NFREQ) {
        if (ssum[tid + 256] != 0.f || scnt[tid + 256] != 0.f) {
            atomicAdd(&g_psum[part][tid + 256], ssum[tid + 256]);
            atomicAdd(&g_pcnt[part][tid + 256], scnt[tid + 256]);
        }
    }
}

// ---------------- kernel 5: nps1D and f1D ----------------------------------------------------
__global__ void k_finalize1d(float* __restrict__ out) {
    int k = threadIdx.x;
    if (k < NFREQ) {
        float s = 0.f, c = 0.f;
#pragma unroll
        for (int p = 0; p < 32; p++) { s += g_psum[p][k]; c += g_pcnt[p][k]; }
        out[k] = s / c;
        out[NFREQ + N * N + k] = 5.0f * (float)k / 256.0f;
    }
}

extern "C" void kernel_launch(void* const* d_in, const int* in_sizes, int n_in,
                              void* d_out, int out_size) {
    const float* x = (const float*)d_in[0];
    float* out = (float*)d_out;

    k_init<<<1024, 256>>>();
    k_meanpart<<<NIMG * 8, 256>>>(x);
    k_meanfin<<<1, 128>>>();
    k_rowfft<<<NIMG * 64, 256>>>(x);
    k_colfft<<<33 * 16, 512>>>();
    k_finalize2d<<<N, 256>>>(out);
    k_finalize1d<<<1, NFREQ>>>(out);
}

// round 4
// speedup vs baseline: 2.1173x; 1.3182x over previous
#include <cuda_runtime.h>
#include <math.h>

#define N 512
#define NIMG 128
#define NFREQ 257
#define RS 65536                 // image scratch k-stride in float2 (=128*512)

// ---------------- device scratch ------------------------------------------------------------
static __device__ float2 g_scratch[(size_t)NFREQ * RS];   // c-major: [k][b*512+r], ~135MB
static __device__ float2 g_hrow[(size_t)NFREQ * N];       // rowFFT of hann, [k][r], 1MB
static __device__ float2 g_tw[N];                         // W_512^k
static __device__ float  g_hann[N * N];                   // window table, 1MB
static __device__ float  g_parts[NIMG * 64];
static __device__ float  g_hparts[64];
static __device__ float  g_mean[NIMG];
static __device__ float  g_accum[N * NFREQ];              // half-plane sum |F|^2 (unshifted)
static __device__ float  g_psum[32][NFREQ];
static __device__ float  g_pcnt[32][NFREQ];

__device__ __forceinline__ int adr2(int i) { return i + (i >> 3); }
__device__ __forceinline__ int rev8(int i) { return ((i & 7) << 6) | (i & 56) | (i >> 6); }

// ---- packed f32x2 helpers -------------------------------------------------------------------
union F2U { float2 f; unsigned long long u; };
__device__ __forceinline__ float2 padd(float2 a, float2 b) {
    F2U A, B, C; A.f = a; B.f = b;
    asm("add.rn.f32x2 %0, %1, %2;" : "=l"(C.u) : "l"(A.u), "l"(B.u));
    return C.f;
}
__device__ __forceinline__ float2 psub(float2 a, float2 b) {
    F2U A, B, C; A.f = a; B.f = b;
    asm("fma.rn.f32x2 %0, %1, %2, %3;"
        : "=l"(C.u) : "l"(B.u), "l"(0xBF800000BF800000ULL), "l"(A.u));
    return C.f;
}
__device__ __forceinline__ float2 cmulf2(float2 a, float2 w) {
    return make_float2(a.x * w.x - a.y * w.y, a.x * w.y + a.y * w.x);
}

// ---- natural-order 8-point DFT --------------------------------------------------------------
__device__ __forceinline__ void dft8(float2* t) {
    float2 b0 = t[0], b1 = t[4], b2 = t[2], b3 = t[6];
    float2 b4 = t[1], b5 = t[5], b6 = t[3], b7 = t[7];
    float2 u0 = padd(b0, b1), u1 = psub(b0, b1), u2 = padd(b2, b3), u3 = psub(b2, b3);
    float2 u4 = padd(b4, b5), u5 = psub(b4, b5), u6 = padd(b6, b7), u7 = psub(b6, b7);
    float2 v0 = padd(u0, u2), v2 = psub(u0, u2);
    float2 v1 = make_float2(u1.x + u3.y, u1.y - u3.x);
    float2 v3 = make_float2(u1.x - u3.y, u1.y + u3.x);
    float2 v4 = padd(u4, u6), v6 = psub(u4, u6);
    float2 v5 = make_float2(u5.x + u7.y, u5.y - u7.x);
    float2 v7 = make_float2(u5.x - u7.y, u5.y + u7.x);
    const float C = 0.70710678118654752f;
    float2 a5 = make_float2(C * (v5.x + v5.y), C * (v5.y - v5.x));
    float2 a7 = make_float2(C * (v7.y - v7.x), -C * (v7.x + v7.y));
    t[0] = padd(v0, v4); t[4] = psub(v0, v4);
    t[1] = padd(v1, a5); t[5] = psub(v1, a5);
    t[2] = make_float2(v2.x + v6.y, v2.y - v6.x);
    t[6] = make_float2(v2.x - v6.y, v2.y + v6.x);
    t[3] = padd(v3, a7); t[7] = psub(v3, a7);
}

// ---------------- kernel 0: init (twiddles, hann table, zero accumulators) -------------------
__global__ void k_init() {
    int p = blockIdx.x * blockDim.x + threadIdx.x;   // 0..262143
    {   // hann window
        int i = p >> 9, j = p & 511;
        const float STEP = 512.0f / 511.0f;
        float lc = fmaf((float)j, STEP, -256.0f);
        float lr = fmaf((float)i, STEP, -256.0f);
        float rd = sqrtf(lc * lc + lr * lr);
        g_hann[p] = (rd > 256.0f) ? 0.0f : 0.5f * (1.0f + cospif(rd * (1.0f / 256.0f)));
    }
    if (p < N * NFREQ) g_accum[p] = 0.f;
    if (p < N) {
        double ang = -6.283185307179586476925286766559 * (double)p / 512.0;
        g_tw[p] = make_float2((float)cos(ang), (float)sin(ang));
    }
    if (p < 32 * NFREQ) { ((float*)g_psum)[p] = 0.f; ((float*)g_pcnt)[p] = 0.f; }
}

// ---------------- kernel 1: DIF row FFTs, 2 real rows packed per FFT -------------------------
// 4 FFTs (8 rows) per 256-thread block. src==nullptr -> rowFFT of the window itself.
// Stage 0 fused with the global load (registers); also emits per-block pixel sums.
__global__ void __launch_bounds__(256) k_rowfft(const float* __restrict__ src,
                                                float2* __restrict__ dst,
                                                float* __restrict__ parts,
                                                int kstride) {
    __shared__ float2 sm[4][576];
    __shared__ float red[8];
    int b   = blockIdx.x >> 6;
    int r0  = (blockIdx.x & 63) << 3;
    int tid = threadIdx.x;
    int f   = tid >> 6, fj = tid & 63;
    int rowA = r0 + 2 * f;
    size_t srcbase = ((size_t)b << 18) + ((size_t)rowA << 9);
    const float* hA = g_hann + (rowA << 9);
    float2* s = sm[f];

    // ---- load + stage 0 (stride 64) in registers ----
    float2 t[8];
    float lsum = 0.f;
#pragma unroll
    for (int m = 0; m < 8; m++) {
        int c = fj + (m << 6);
        float va = src ? src[srcbase + c]       : 1.0f;
        float vb = src ? src[srcbase + 512 + c] : 1.0f;
        lsum += va + vb;
        t[m] = make_float2(va * hA[c], vb * hA[512 + c]);
    }
    dft8(t);
    int pb0 = fj + (fj >> 3);
#pragma unroll
    for (int q = 1; q < 8; q++) t[q] = cmulf2(t[q], g_tw[fj * q]);
#pragma unroll
    for (int q = 0; q < 8; q++) s[pb0 + 72 * q] = t[q];

    // per-block pixel sum (piggybacks on the stage0->1 barrier)
#pragma unroll
    for (int o = 16; o; o >>= 1) lsum += __shfl_down_sync(0xffffffffu, lsum, o);
    if ((tid & 31) == 0) red[tid >> 5] = lsum;
    __syncthreads();
    if (tid == 0) {
        float tot = 0.f;
#pragma unroll
        for (int p = 0; p < 8; p++) tot += red[p];
        parts[blockIdx.x] = tot;
    }

    // ---- stage 1 (stride 8) ----
    {
        int i = fj & 7, q0 = fj >> 3;
        int pb = i + 72 * q0, e = i << 3;
        float2 u[8];
#pragma unroll
        for (int m = 0; m < 8; m++) u[m] = s[pb + 9 * m];
        dft8(u);
#pragma unroll
        for (int q = 1; q < 8; q++) u[q] = cmulf2(u[q], g_tw[e * q]);
#pragma unroll
        for (int q = 0; q < 8; q++) s[pb + 9 * q] = u[q];
    }
    __syncthreads();

    // ---- stage 2 (stride 1), no twiddle ----
    {
        int pb = 9 * fj;
        float2 u[8];
#pragma unroll
        for (int m = 0; m < 8; m++) u[m] = s[pb + m];
        dft8(u);
#pragma unroll
        for (int m = 0; m < 8; m++) s[pb + m] = u[m];
    }
    __syncthreads();

    // ---- Hermitian unpack + k-major (transposed) store: 8-row 64B chunks ----
    int r = tid & 7;             // row within block
    float2* so = sm[r >> 1];
    int kslot = tid >> 3;        // 0..31
#pragma unroll
    for (int it = 0; it < 9; it++) {
        int k = kslot + (it << 5);
        if (k < NFREQ) {
            float2 z = so[adr2(rev8(k))];
            float2 y = so[adr2(rev8((512 - k) & 511))];
            float2 o = (r & 1)
                ? make_float2(0.5f * (z.y + y.y), 0.5f * (y.x - z.x))
                : make_float2(0.5f * (z.x + y.x), 0.5f * (z.y - y.y));
            dst[(size_t)k * kstride + ((size_t)b << 9) + r0 + r] = o;
        }
    }
}

// ---------------- kernel 2: reduce block sums -> per-image means -----------------------------
__global__ void k_meanfin() {
    int i = threadIdx.x;
    if (i < NIMG) {
        float s = 0.f;
#pragma unroll
        for (int p = 0; p < 64; p++) s += g_parts[i * 64 + p];
        g_mean[i] = s * (1.0f / 262144.0f);
    }
}

// ---------------- kernel 3: DIF column FFTs, mean correction, |F|^2 in registers -------------
// 8 cols x 64 threads; 8 images per block; stage 0 from registers, stage 2 -> accumulator.
__global__ void __launch_bounds__(512) k_colfft() {
    __shared__ float2 sm[8][576];
    int ct  = blockIdx.x % 33;
    int grp = blockIdx.x / 33;
    int cl  = threadIdx.x >> 6;
    int fj  = threadIdx.x & 63;
    int c   = (ct << 3) + cl;
    bool valid = (c < NFREQ);
    float2* s = sm[cl];
    size_t cbase = valid ? (size_t)c * RS : 0;
    size_t hbase = valid ? ((size_t)c << 9) : 0;

    int pb0 = fj + (fj >> 3);
    int i1 = fj & 7, q01 = fj >> 3;
    int pb1 = i1 + 72 * q01, e1 = i1 << 3;
    int pb2 = 9 * fj;

    float acc[8];
#pragma unroll
    for (int m = 0; m < 8; m++) acc[m] = 0.f;

    for (int bi = 0; bi < 8; bi++) {
        int b = (grp << 3) + bi;
        float mean = g_mean[b];
        float2 t[8];
        if (valid) {
#pragma unroll
            for (int m = 0; m < 8; m++) {
                int r = fj + (m << 6);
                float2 v  = g_scratch[cbase + ((size_t)b << 9) + r];
                float2 hv = g_hrow[hbase + r];
                t[m] = make_float2(fmaf(-mean, hv.x, v.x), fmaf(-mean, hv.y, v.y));
            }
            dft8(t);
#pragma unroll
            for (int q = 1; q < 8; q++) t[q] = cmulf2(t[q], g_tw[fj * q]);
        } else {
#pragma unroll
            for (int m = 0; m < 8; m++) t[m] = make_float2(0.f, 0.f);
        }
        __syncthreads();                       // prior stage-2 reads done before overwrite
#pragma unroll
        for (int q = 0; q < 8; q++) s[pb0 + 72 * q] = t[q];
        __syncthreads();

        // stage 1
#pragma unroll
        for (int m = 0; m < 8; m++) t[m] = s[pb1 + 9 * m];
        dft8(t);
#pragma unroll
        for (int q = 1; q < 8; q++) t[q] = cmulf2(t[q], g_tw[e1 * q]);
#pragma unroll
        for (int q = 0; q < 8; q++) s[pb1 + 9 * q] = t[q];
        __syncthreads();

        // stage 2 + accumulate (no store; digit-reversed mapping folded into r below)
#pragma unroll
        for (int m = 0; m < 8; m++) t[m] = s[pb2 + m];
        dft8(t);
#pragma unroll
        for (int m = 0; m < 8; m++)
            acc[m] = fmaf(t[m].x, t[m].x, fmaf(t[m].y, t[m].y, acc[m]));
    }

    if (valid) {
        int rlo = ((fj & 7) << 3) + (fj >> 3);
#pragma unroll
        for (int m = 0; m < 8; m++) {
            int r = (m << 6) + rlo;            // = rev8(8*fj+m)
            atomicAdd(&g_accum[r * NFREQ + c], acc[m]);
        }
    }
}

// ---------------- kernel 4: nps2D + two-level radial binning ---------------------------------
__global__ void __launch_bounds__(256) k_finalize2d(float* __restrict__ out) {
    __shared__ float ssum[NFREQ];
    __shared__ float scnt[NFREQ];
    int i = blockIdx.x;
    int tid = threadIdx.x;
    if (tid < NFREQ) { ssum[tid] = 0.f; scnt[tid] = 0.f; }
    if (tid + 256 < NFREQ) { ssum[tid + 256] = 0.f; scnt[tid + 256] = 0.f; }
    __syncthreads();

    const float SC = (float)(0.01 / (262144.0 * 128.0));
    int xi = i - 256;
#pragma unroll
    for (int h = 0; h < 2; h++) {
        int j = tid + (h << 8);
        int u = i ^ 256, v = j ^ 256;
        if (v > 256) { u = (512 - u) & 511; v = 512 - v; }
        float val = g_accum[u * NFREQ + v] * SC;
        out[NFREQ + (i << 9) + j] = val;
        int yj = j - 256;
        int rad = __double2int_rn(sqrt((double)(xi * xi + yj * yj)));
        if (rad < NFREQ) {
            atomicAdd(&ssum[rad], val);
            atomicAdd(&scnt[rad], 1.0f);
        }
    }
    __syncthreads();

    int part = i & 31;
    if (tid < NFREQ && (ssum[tid] != 0.f || scnt[tid] != 0.f)) {
        atomicAdd(&g_psum[part][tid], ssum[tid]);
        atomicAdd(&g_pcnt[part][tid], scnt[tid]);
    }
    if (tid + 256 < NFREQ && (ssum[tid + 256] != 0.f || scnt[tid + 256] != 0.f)) {
        atomicAdd(&g_psum[part][tid + 256], ssum[tid + 256]);
        atomicAdd(&g_pcnt[part][tid + 256], scnt[tid + 256]);
    }
}

// ---------------- kernel 5: nps1D and f1D ----------------------------------------------------
__global__ void k_finalize1d(float* __restrict__ out) {
    int k = threadIdx.x;
    if (k < NFREQ) {
        float s = 0.f, c = 0.f;
#pragma unroll
        for (int p = 0; p < 32; p++) { s += g_psum[p][k]; c += g_pcnt[p][k]; }
        out[k] = s / c;
        out[NFREQ + N * N + k] = 5.0f * (float)k / 256.0f;
    }
}

extern "C" void kernel_launch(void* const* d_in, const int* in_sizes, int n_in,
                              void* d_out, int out_size) {
    const float* x = (const float*)d_in[0];
    float* out = (float*)d_out;
    float2* scr  = g_scratch;   // silence unused warnings via direct refs below
    (void)scr;

    float* pparts;  cudaGetSymbolAddress((void**)&pparts,  g_parts);
    float* phparts; cudaGetSymbolAddress((void**)&phparts, g_hparts);
    float2* pscr;   cudaGetSymbolAddress((void**)&pscr,    g_scratch);
    float2* phrow;  cudaGetSymbolAddress((void**)&phrow,   g_hrow);

    k_init<<<1024, 256>>>();
    k_rowfft<<<NIMG * 64, 256>>>(x, pscr, pparts, RS);          // images: FFT(v*h)
    k_rowfft<<<64, 256>>>(nullptr, phrow, phparts, N);          // window: FFT(h)
    k_meanfin<<<1, 128>>>();
    k_colfft<<<33 * 16, 512>>>();
    k_finalize2d<<<N, 256>>>(out);
    k_finalize1d<<<1, NFREQ>>>(out);
}

// round 5
// speedup vs baseline: 2.3403x; 1.1053x over previous
#include <cuda_runtime.h>
#include <math.h>

#define N 512
#define NIMG 128
#define NFREQ 257
#define RS 65536                 // image scratch k-stride in float2 (=128*512)

// ---------------- device scratch ------------------------------------------------------------
static __device__ float2 g_scratch[(size_t)NFREQ * RS];   // c-major: [k][b*512+r], ~135MB
static __device__ float2 g_hrow[(size_t)NFREQ * N];       // rowFFT of hann, [k][r], 1MB
static __device__ float2 g_tw[N];                         // W_512^k
static __device__ float  g_hann[N * N];                   // window table, 1MB
static __device__ float  g_parts[NIMG * 64];
static __device__ float  g_hparts[64];
static __device__ float  g_accum[N * NFREQ];              // half-plane sum |F|^2 (unshifted)
static __device__ float  g_psum[32][NFREQ];
static __device__ float  g_pcnt[32][NFREQ];

__device__ __forceinline__ int adr2(int i) { return i + (i >> 3); }
__device__ __forceinline__ int rev8(int i) { return ((i & 7) << 6) | (i & 56) | (i >> 6); }

// ---- packed f32x2 helpers -------------------------------------------------------------------
union F2U { float2 f; unsigned long long u; };
__device__ __forceinline__ float2 padd(float2 a, float2 b) {
    F2U A, B, C; A.f = a; B.f = b;
    asm("add.rn.f32x2 %0, %1, %2;" : "=l"(C.u) : "l"(A.u), "l"(B.u));
    return C.f;
}
__device__ __forceinline__ float2 psub(float2 a, float2 b) {
    F2U A, B, C; A.f = a; B.f = b;
    asm("fma.rn.f32x2 %0, %1, %2, %3;"
        : "=l"(C.u) : "l"(B.u), "l"(0xBF800000BF800000ULL), "l"(A.u));
    return C.f;
}
__device__ __forceinline__ float2 cmulf2(float2 a, float2 w) {
    return make_float2(a.x * w.x - a.y * w.y, a.x * w.y + a.y * w.x);
}

// ---- natural-order 8-point DFT --------------------------------------------------------------
__device__ __forceinline__ void dft8(float2* t) {
    float2 b0 = t[0], b1 = t[4], b2 = t[2], b3 = t[6];
    float2 b4 = t[1], b5 = t[5], b6 = t[3], b7 = t[7];
    float2 u0 = padd(b0, b1), u1 = psub(b0, b1), u2 = padd(b2, b3), u3 = psub(b2, b3);
    float2 u4 = padd(b4, b5), u5 = psub(b4, b5), u6 = padd(b6, b7), u7 = psub(b6, b7);
    float2 v0 = padd(u0, u2), v2 = psub(u0, u2);
    float2 v1 = make_float2(u1.x + u3.y, u1.y - u3.x);
    float2 v3 = make_float2(u1.x - u3.y, u1.y + u3.x);
    float2 v4 = padd(u4, u6), v6 = psub(u4, u6);
    float2 v5 = make_float2(u5.x + u7.y, u5.y - u7.x);
    float2 v7 = make_float2(u5.x - u7.y, u5.y + u7.x);
    const float C = 0.70710678118654752f;
    float2 a5 = make_float2(C * (v5.x + v5.y), C * (v5.y - v5.x));
    float2 a7 = make_float2(C * (v7.y - v7.x), -C * (v7.x + v7.y));
    t[0] = padd(v0, v4); t[4] = psub(v0, v4);
    t[1] = padd(v1, a5); t[5] = psub(v1, a5);
    t[2] = make_float2(v2.x + v6.y, v2.y - v6.x);
    t[6] = make_float2(v2.x - v6.y, v2.y + v6.x);
    t[3] = padd(v3, a7); t[7] = psub(v3, a7);
}

// ---------------- kernel 0: init (twiddles, hann table, zero accumulators) -------------------
__global__ void k_init() {
    int p = blockIdx.x * blockDim.x + threadIdx.x;
    {
        int i = p >> 9, j = p & 511;
        const float STEP = 512.0f / 511.0f;
        float lc = fmaf((float)j, STEP, -256.0f);
        float lr = fmaf((float)i, STEP, -256.0f);
        float rd = sqrtf(lc * lc + lr * lr);
        g_hann[p] = (rd > 256.0f) ? 0.0f : 0.5f * (1.0f + cospif(rd * (1.0f / 256.0f)));
    }
    if (p < N * NFREQ) g_accum[p] = 0.f;
    if (p < N) {
        double ang = -6.283185307179586476925286766559 * (double)p / 512.0;
        g_tw[p] = make_float2((float)cos(ang), (float)sin(ang));
    }
    if (p < 32 * NFREQ) { ((float*)g_psum)[p] = 0.f; ((float*)g_pcnt)[p] = 0.f; }
}

// ---------------- kernel 1: DIF row FFTs, 2 real rows packed per FFT -------------------------
__global__ void __launch_bounds__(256) k_rowfft(const float* __restrict__ src,
                                                float2* __restrict__ dst,
                                                float* __restrict__ parts,
                                                int kstride) {
    __shared__ float2 sm[4][576];
    __shared__ float red[8];
    int b   = blockIdx.x >> 6;
    int r0  = (blockIdx.x & 63) << 3;
    int tid = threadIdx.x;
    int f   = tid >> 6, fj = tid & 63;
    int rowA = r0 + 2 * f;
    size_t srcbase = ((size_t)b << 18) + ((size_t)rowA << 9);
    const float* hA = g_hann + (rowA << 9);
    float2* s = sm[f];

    // ---- load + stage 0 (stride 64) in registers ----
    float2 t[8];
    float lsum = 0.f;
#pragma unroll
    for (int m = 0; m < 8; m++) {
        int c = fj + (m << 6);
        float va = src ? src[srcbase + c]       : 1.0f;
        float vb = src ? src[srcbase + 512 + c] : 1.0f;
        lsum += va + vb;
        t[m] = make_float2(va * hA[c], vb * hA[512 + c]);
    }
    dft8(t);
    int pb0 = fj + (fj >> 3);
#pragma unroll
    for (int q = 1; q < 8; q++) t[q] = cmulf2(t[q], g_tw[fj * q]);
#pragma unroll
    for (int q = 0; q < 8; q++) s[pb0 + 72 * q] = t[q];

    // per-block pixel sum (piggybacks on the stage0->1 barrier)
#pragma unroll
    for (int o = 16; o; o >>= 1) lsum += __shfl_down_sync(0xffffffffu, lsum, o);
    if ((tid & 31) == 0) red[tid >> 5] = lsum;
    __syncthreads();
    if (tid == 0) {
        float tot = 0.f;
#pragma unroll
        for (int p = 0; p < 8; p++) tot += red[p];
        parts[blockIdx.x] = tot;
    }

    // ---- stage 1 (stride 8) ----
    {
        int i = fj & 7, q0 = fj >> 3;
        int pb = i + 72 * q0, e = i << 3;
        float2 u[8];
#pragma unroll
        for (int m = 0; m < 8; m++) u[m] = s[pb + 9 * m];
        dft8(u);
#pragma unroll
        for (int q = 1; q < 8; q++) u[q] = cmulf2(u[q], g_tw[e * q]);
#pragma unroll
        for (int q = 0; q < 8; q++) s[pb + 9 * q] = u[q];
    }
    __syncthreads();

    // ---- stage 2 (stride 1), no twiddle ----
    {
        int pb = 9 * fj;
        float2 u[8];
#pragma unroll
        for (int m = 0; m < 8; m++) u[m] = s[pb + m];
        dft8(u);
#pragma unroll
        for (int m = 0; m < 8; m++) s[pb + m] = u[m];
    }
    __syncthreads();

    // ---- Hermitian unpack + k-major (transposed) store ----
    int r = tid & 7;
    float2* so = sm[r >> 1];
    int kslot = tid >> 3;
#pragma unroll
    for (int it = 0; it < 9; it++) {
        int k = kslot + (it << 5);
        if (k < NFREQ) {
            float2 z = so[adr2(rev8(k))];
            float2 y = so[adr2(rev8((512 - k) & 511))];
            float2 o = (r & 1)
                ? make_float2(0.5f * (z.y + y.y), 0.5f * (y.x - z.x))
                : make_float2(0.5f * (z.x + y.x), 0.5f * (z.y - y.y));
            dst[(size_t)k * kstride + ((size_t)b << 9) + r0 + r] = o;
        }
    }
}

// ---------------- kernel 2: DIF column FFTs, fused mean reduction, 16 images/block -----------
__global__ void __launch_bounds__(512, 2) k_colfft() {
    __shared__ float2 sm[8][576];
    __shared__ float wsum[32];
    __shared__ float smean[16];
    int ct  = blockIdx.x % 33;
    int grp = blockIdx.x / 33;               // 0..7 : 16 images each
    int cl  = threadIdx.x >> 6;
    int fj  = threadIdx.x & 63;
    int c   = (ct << 3) + cl;
    bool valid = (c < NFREQ);
    float2* s = sm[cl];
    size_t cbase = valid ? (size_t)c * RS : 0;
    int b0 = grp << 4;

    // ---- cached correction vector (invariant over image loop) ----
    float2 hv[8];
    size_t hbase = valid ? ((size_t)c << 9) : 0;
#pragma unroll
    for (int m = 0; m < 8; m++)
        hv[m] = valid ? g_hrow[hbase + fj + (m << 6)] : make_float2(0.f, 0.f);

    // ---- prefetch image 0 ----
    float2 t[8];
#pragma unroll
    for (int m = 0; m < 8; m++)
        t[m] = valid ? g_scratch[cbase + ((size_t)b0 << 9) + fj + (m << 6)]
                     : make_float2(0.f, 0.f);

    // ---- fused per-image means from g_parts (16 images x 64 parts = 1024 floats) ----
    {
        int base = b0 << 6;
        float v1 = g_parts[base + threadIdx.x];
        float v2 = g_parts[base + 512 + threadIdx.x];
#pragma unroll
        for (int o = 16; o; o >>= 1) {
            v1 += __shfl_down_sync(0xffffffffu, v1, o);
            v2 += __shfl_down_sync(0xffffffffu, v2, o);
        }
        int w = threadIdx.x >> 5;
        if ((threadIdx.x & 31) == 0) { wsum[w] = v1; wsum[16 + w] = v2; }
        __syncthreads();
        if (threadIdx.x < 16)
            smean[threadIdx.x] = (wsum[2 * threadIdx.x] + wsum[2 * threadIdx.x + 1])
                                 * (1.0f / 262144.0f);
        __syncthreads();
    }

    int pb0 = fj + (fj >> 3);
    int i1 = fj & 7, q01 = fj >> 3;
    int pb1 = i1 + 72 * q01, e1 = i1 << 3;
    int pb2 = 9 * fj;

    float acc[8];
#pragma unroll
    for (int m = 0; m < 8; m++) acc[m] = 0.f;

    for (int bi = 0; bi < 16; bi++) {
        float mean = smean[bi];

        // stage 0 on current image (registers): correction + dft8 + twiddle
        float2 tc[8];
#pragma unroll
        for (int m = 0; m < 8; m++)
            tc[m] = make_float2(fmaf(-mean, hv[m].x, t[m].x),
                                fmaf(-mean, hv[m].y, t[m].y));
        dft8(tc);
#pragma unroll
        for (int q = 1; q < 8; q++) tc[q] = cmulf2(tc[q], g_tw[fj * q]);

        __syncthreads();                       // prev stage-2 reads complete
#pragma unroll
        for (int q = 0; q < 8; q++) s[pb0 + 72 * q] = tc[q];

        // prefetch next image into (now dead) t — hidden across 2 barriers + stages 1-2
        if (bi < 15 && valid) {
            int b = b0 + bi + 1;
#pragma unroll
            for (int m = 0; m < 8; m++)
                t[m] = g_scratch[cbase + ((size_t)b << 9) + fj + (m << 6)];
        }
        __syncthreads();

        // stage 1
        float2 u[8];
#pragma unroll
        for (int m = 0; m < 8; m++) u[m] = s[pb1 + 9 * m];
        dft8(u);
#pragma unroll
        for (int q = 1; q < 8; q++) u[q] = cmulf2(u[q], g_tw[e1 * q]);
#pragma unroll
        for (int q = 0; q < 8; q++) s[pb1 + 9 * q] = u[q];
        __syncthreads();

        // stage 2 + accumulate (no store)
#pragma unroll
        for (int m = 0; m < 8; m++) u[m] = s[pb2 + m];
        dft8(u);
#pragma unroll
        for (int m = 0; m < 8; m++)
            acc[m] = fmaf(u[m].x, u[m].x, fmaf(u[m].y, u[m].y, acc[m]));
    }

    if (valid) {
        int rlo = ((fj & 7) << 3) + (fj >> 3);
#pragma unroll
        for (int m = 0; m < 8; m++) {
            int r = (m << 6) + rlo;            // = rev8(8*fj+m)
            atomicAdd(&g_accum[r * NFREQ + c], acc[m]);
        }
    }
}

// ---------------- kernel 3: nps2D + two-level radial binning ---------------------------------
__global__ void __launch_bounds__(256) k_finalize2d(float* __restrict__ out) {
    __shared__ float ssum[NFREQ];
    __shared__ float scnt[NFREQ];
    int i = blockIdx.x;
    int tid = threadIdx.x;
    if (tid < NFREQ) { ssum[tid] = 0.f; scnt[tid] = 0.f; }
    if (tid + 256 < NFREQ) { ssum[tid + 256] = 0.f; scnt[tid + 256] = 0.f; }
    __syncthreads();

    const float SC = (float)(0.01 / (262144.0 * 128.0));
    int xi = i - 256;
#pragma unroll
    for (int h = 0; h < 2; h++) {
        int j = tid + (h << 8);
        int u = i ^ 256, v = j ^ 256;
        if (v > 256) { u = (512 - u) & 511; v = 512 - v; }
        float val = g_accum[u * NFREQ + v] * SC;
        out[NFREQ + (i << 9) + j] = val;
        int yj = j - 256;
        int rad = __double2int_rn(sqrt((double)(xi * xi + yj * yj)));
        if (rad < NFREQ) {
            atomicAdd(&ssum[rad], val);
            atomicAdd(&scnt[rad], 1.0f);
        }
    }
    __syncthreads();

    int part = i & 31;
    if (tid < NFREQ && (ssum[tid] != 0.f || scnt[tid] != 0.f)) {
        atomicAdd(&g_psum[part][tid], ssum[tid]);
        atomicAdd(&g_pcnt[part][tid], scnt[tid]);
    }
    if (tid + 256 < NFREQ && (ssum[tid + 256] != 0.f || scnt[tid + 256] != 0.f)) {
        atomicAdd(&g_psum[part][tid + 256], ssum[tid + 256]);
        atomicAdd(&g_pcnt[part][tid + 256], scnt[tid + 256]);
    }
}

// ---------------- kernel 4: nps1D and f1D ----------------------------------------------------
__global__ void k_finalize1d(float* __restrict__ out) {
    int k = threadIdx.x;
    if (k < NFREQ) {
        float s = 0.f, c = 0.f;
#pragma unroll
        for (int p = 0; p < 32; p++) { s += g_psum[p][k]; c += g_pcnt[p][k]; }
        out[k] = s / c;
        out[NFREQ + N * N + k] = 5.0f * (float)k / 256.0f;
    }
}

extern "C" void kernel_launch(void* const* d_in, const int* in_sizes, int n_in,
                              void* d_out, int out_size) {
    const float* x = (const float*)d_in[0];
    float* out = (float*)d_out;

    float* pparts;  cudaGetSymbolAddress((void**)&pparts,  g_parts);
    float* phparts; cudaGetSymbolAddress((void**)&phparts, g_hparts);
    float2* pscr;   cudaGetSymbolAddress((void**)&pscr,    g_scratch);
    float2* phrow;  cudaGetSymbolAddress((void**)&phrow,   g_hrow);

    k_init<<<1024, 256>>>();
    k_rowfft<<<NIMG * 64, 256>>>(x, pscr, pparts, RS);          // images: FFT(v*h)
    k_rowfft<<<64, 256>>>(nullptr, phrow, phparts, N);          // window: FFT(h)
    k_colfft<<<33 * 8, 512>>>();                                // 16 images per block
    k_finalize2d<<<N, 256>>>(out);
    k_finalize1d<<<1, NFREQ>>>(out);
}